// round 9
// baseline (speedup 1.0000x reference)
#include <cuda_runtime.h>

// labels [16, 8, 512, 512] float32
#define HH 512
#define WW 512
#define NIMG 128                  // 16*8
#define ROWS 32                   // output rows per band
#define BANDS (HH / ROWS)         // 16
#define STRIPS 4                  // 4 strips of 128 cols (4 cols/thread)
#define WPB 4                     // warps per block (128 threads)
#define NBLOCKS ((NIMG * BANDS * STRIPS) / WPB)   // 2048
#define INV_N (1.0f / 33554432.0f)

__device__ float g_partials[NBLOCKS];
__device__ unsigned int g_counter = 0;

__global__ __launch_bounds__(128) void open_mse_kernel(const float* __restrict__ x,
                                                       float* __restrict__ out) {
    const int tid  = threadIdx.x;
    const int wid  = tid >> 5;
    const int lane = tid & 31;
    const int gw   = blockIdx.x * WPB + wid;     // [0, 8192)

    const int strip = gw & 3;                    // 0..3
    const int band  = (gw >> 2) & (BANDS - 1);   // 0..15
    const int img   = gw >> 6;                   // 0..127

    const int c0 = strip * 128;
    const int r0 = band * ROWS;
    const int r1 = r0 + ROWS;
    const bool leftEdge  = (c0 == 0);
    const bool rightEdge = (c0 + 128 >= WW);

    const float* base = x + (size_t)img * (HH * WW);
    const int c = c0 + lane * 4;
    const bool doL = (lane == 0)  && !leftEdge;
    const bool doH = (lane == 31) && !rightEdge;
    const int haloL = leftEdge ? 0 : (c0 - 1);
    const int haloR = rightEdge ? (WW - 1) : (c0 + 128);

    float rm_prev[4], er_prev[4], x_prev[4];
    float rmH_prev, erH_prev = 0.f;
    float acc = 0.f;

    // ---- prologue: rowmin of row ra = max(r0-1, 0)  (reflect at top) ----
    {
        const int ra = (r0 > 0) ? (r0 - 1) : 0;
        float4 v = *(const float4*)(base + (size_t)ra * WW + c);
        float a[4] = {v.x, v.y, v.z, v.w};
        float xL = doL ? base[(size_t)ra * WW + haloL] : 0.f;
        float xH = doH ? base[(size_t)ra * WW + haloR] : 0.f;
        float left = __shfl_up_sync(0xffffffffu, a[3], 1);
        if (lane == 0) left = leftEdge ? a[0] : xL;
        rm_prev[0] = fminf(left, a[0]);
        #pragma unroll
        for (int j = 1; j < 4; ++j) rm_prev[j] = fminf(a[j - 1], a[j]);
        rmH_prev = fminf(a[3], xH);
    }

    const int e_max = (r1 < HH) ? r1 : (HH - 1);

    // bumped pointers, pointing at row r0+2 after the two pipeline fills
    const float4* p  = (const float4*)(base + (size_t)r0 * WW + c);
    const float*  pL = base + (size_t)r0 * WW + haloL;
    const float*  pH = base + (size_t)r0 * WW + haloR;

    // depth-2 pipeline fill: rows r0 and r0+1 (r0+1 <= 481, always in-bounds)
    float4 vA = p[0];
    float  xLA = doL ? *pL : 0.f;
    float  xHA = doH ? *pH : 0.f;
    p += WW / 4; pL += WW; pH += WW;

    float4 vB = p[0];
    float  xLB = doL ? *pL : 0.f;
    float  xHB = doH ? *pH : 0.f;
    p += WW / 4; pL += WW; pH += WW;

    // ---- peeled first row: e = r0 (erosion only, no output) ----
    {
        float a[4] = {vA.x, vA.y, vA.z, vA.w};
        float xL = xLA, xH = xHA;
        vA = vB; xLA = xLB; xHA = xHB;
        if (r0 + 2 <= e_max) {                 // prefetch row r0+2
            vB = p[0];
            xLB = doL ? *pL : 0.f;
            xHB = doH ? *pH : 0.f;
        }
        p += WW / 4; pL += WW; pH += WW;

        float left = __shfl_up_sync(0xffffffffu, a[3], 1);
        if (lane == 0) left = leftEdge ? a[0] : xL;
        float rm[4];
        rm[0] = fminf(left, a[0]);
        #pragma unroll
        for (int j = 1; j < 4; ++j) rm[j] = fminf(a[j - 1], a[j]);
        #pragma unroll
        for (int j = 0; j < 4; ++j) {
            er_prev[j] = fminf(rm_prev[j], rm[j]);
            rm_prev[j] = rm[j];
            x_prev[j]  = a[j];
        }
        float rmH = fminf(a[3], xH);
        erH_prev = fminf(rmH_prev, rmH);
        rmH_prev = rmH;
    }

    // ---- steady state: e = r0+1 .. e_max, output row e-1 each iter ----
    for (int e = r0 + 1; e <= e_max; ++e) {
        float a[4] = {vA.x, vA.y, vA.z, vA.w};
        float xL = xLA, xH = xHA;
        vA = vB; xLA = xLB; xHA = xHB;
        if (e + 2 <= e_max) {                  // prefetch row e+2
            vB = p[0];
            xLB = doL ? *pL : 0.f;
            xHB = doH ? *pH : 0.f;
        }
        p += WW / 4; pL += WW; pH += WW;       // bump only, never deref OOB

        // horizontal min (erosion offsets {-1,0}, reflect at col 0)
        float left = __shfl_up_sync(0xffffffffu, a[3], 1);
        if (lane == 0) left = leftEdge ? a[0] : xL;
        float rm[4];
        rm[0] = fminf(left, a[0]);
        #pragma unroll
        for (int j = 1; j < 4; ++j) rm[j] = fminf(a[j - 1], a[j]);

        // vertical min -> eroded row e; vertical max with previous eroded row
        float er[4], vm[4];
        #pragma unroll
        for (int j = 0; j < 4; ++j) {
            er[j] = fminf(rm_prev[j], rm[j]);
            vm[j] = fmaxf(er_prev[j], er[j]);
        }
        const float rmH = fminf(a[3], xH);
        const float erH = fminf(rmH_prev, rmH);
        const float vmH = fmaxf(erH_prev, erH);

        // horizontal max (dilation offsets {0,+1}, clamp at right edge)
        float right = __shfl_down_sync(0xffffffffu, vm[0], 1);
        if (lane == 31) right = rightEdge ? vm[3] : vmH;
        float op[4];
        #pragma unroll
        for (int j = 0; j < 3; ++j) op[j] = fmaxf(vm[j], vm[j + 1]);
        op[3] = fmaxf(vm[3], right);

        #pragma unroll
        for (int j = 0; j < 4; ++j) {
            const float d = x_prev[j] - op[j];
            acc += d * d;
        }

        #pragma unroll
        for (int j = 0; j < 4; ++j) {
            er_prev[j] = er[j];
            rm_prev[j] = rm[j];
            x_prev[j]  = a[j];
        }
        erH_prev = erH; rmH_prev = rmH;
    }

    // ---- epilogue: bottom band emits row H-1 (dilation clamps i+1 -> H-1) ----
    if (r1 == HH) {
        float right = __shfl_down_sync(0xffffffffu, er_prev[0], 1);
        if (lane == 31) right = rightEdge ? er_prev[3] : erH_prev;
        float op[4];
        #pragma unroll
        for (int j = 0; j < 3; ++j) op[j] = fmaxf(er_prev[j], er_prev[j + 1]);
        op[3] = fmaxf(er_prev[3], right);
        #pragma unroll
        for (int j = 0; j < 4; ++j) {
            const float d = x_prev[j] - op[j];
            acc += d * d;
        }
    }

    // ---- block reduction -> g_partials[blockIdx.x] ----
    #pragma unroll
    for (int o = 16; o > 0; o >>= 1)
        acc += __shfl_xor_sync(0xffffffffu, acc, o);

    __shared__ float s[WPB];
    __shared__ bool s_last;
    if (lane == 0) s[wid] = acc;
    __syncthreads();
    if (tid == 0) {
        float t = 0.f;
        #pragma unroll
        for (int i = 0; i < WPB; ++i) t += s[i];
        g_partials[blockIdx.x] = t;
        __threadfence();
        unsigned int old = atomicAdd(&g_counter, 1u);
        s_last = (old == NBLOCKS - 1);
    }
    __syncthreads();

    // ---- last block: deterministic fixed-order final reduction ----
    if (s_last) {
        float a = 0.f;
        for (int i = tid; i < NBLOCKS; i += 128) a += g_partials[i];
        #pragma unroll
        for (int o = 16; o > 0; o >>= 1)
            a += __shfl_xor_sync(0xffffffffu, a, o);
        __shared__ float s2[WPB];
        if (lane == 0) s2[wid] = a;
        __syncthreads();
        if (tid == 0) {
            float t = 0.f;
            #pragma unroll
            for (int i = 0; i < WPB; ++i) t += s2[i];
            out[0] = t * INV_N;
            g_counter = 0;   // self-reset for next launch / graph replay
        }
    }
}

extern "C" void kernel_launch(void* const* d_in, const int* in_sizes, int n_in,
                              void* d_out, int out_size) {
    (void)in_sizes; (void)n_in; (void)out_size;
    const float* labels = (const float*)d_in[0];
    float* out = (float*)d_out;
    open_mse_kernel<<<NBLOCKS, 128>>>(labels, out);
}

// round 10
// speedup vs baseline: 1.2222x; 1.2222x over previous
#include <cuda_runtime.h>

// labels [16, 8, 512, 512] float32
#define HH 512
#define WW 512
#define NIMG 128                  // 16*8
#define ROWS 32                   // output rows per band
#define BANDS (HH / ROWS)         // 16
#define STRIPS 4                  // 4 strips of 128 cols (4 cols/thread)
#define WPB 4                     // warps per block (128 threads)
#define NBLOCKS ((NIMG * BANDS * STRIPS) / WPB)   // 2048
#define INV_N (1.0f / 33554432.0f)

__device__ float g_partials[NBLOCKS];
__device__ unsigned int g_counter = 0;

__global__ __launch_bounds__(128) void open_mse_kernel(const float* __restrict__ x,
                                                       float* __restrict__ out) {
    const int tid  = threadIdx.x;
    const int wid  = tid >> 5;
    const int lane = tid & 31;
    const int gw   = blockIdx.x * WPB + wid;     // [0, 8192)

    const int strip = gw & 3;                    // 0..3
    const int band  = (gw >> 2) & (BANDS - 1);   // 0..15
    const int img   = gw >> 6;                   // 0..127

    const int c0 = strip * 128;
    const int r0 = band * ROWS;
    const int r1 = r0 + ROWS;
    const bool leftEdge  = (c0 == 0);
    const bool rightEdge = (c0 + 128 >= WW);

    const float* base = x + (size_t)img * (HH * WW);
    const int c = c0 + lane * 4;
    const bool doL = (lane == 0)  && !leftEdge;
    const bool doH = (lane == 31) && !rightEdge;
    const int haloL = leftEdge ? 0 : (c0 - 1);
    const int haloR = rightEdge ? (WW - 1) : (c0 + 128);

    float rm_prev[4], er_prev[4], x_prev[4];
    float rmH_prev, erH_prev = 0.f;
    float acc = 0.f;

    // ---- prologue: rowmin of row ra = max(r0-1, 0)  (reflect at top) ----
    {
        const int ra = (r0 > 0) ? (r0 - 1) : 0;
        float4 v = *(const float4*)(base + (size_t)ra * WW + c);
        float a[4] = {v.x, v.y, v.z, v.w};
        float xL = doL ? base[(size_t)ra * WW + haloL] : 0.f;
        float xH = doH ? base[(size_t)ra * WW + haloR] : 0.f;
        float left = __shfl_up_sync(0xffffffffu, a[3], 1);
        if (lane == 0) left = leftEdge ? a[0] : xL;
        rm_prev[0] = fminf(left, a[0]);
        #pragma unroll
        for (int j = 1; j < 4; ++j) rm_prev[j] = fminf(a[j - 1], a[j]);
        rmH_prev = fminf(a[3], xH);
    }

    // ---- peeled row r0: erosion only (no output) ----
    {
        float4 v = *(const float4*)(base + (size_t)r0 * WW + c);
        float a[4] = {v.x, v.y, v.z, v.w};
        float xL = doL ? base[(size_t)r0 * WW + haloL] : 0.f;
        float xH = doH ? base[(size_t)r0 * WW + haloR] : 0.f;
        float left = __shfl_up_sync(0xffffffffu, a[3], 1);
        if (lane == 0) left = leftEdge ? a[0] : xL;
        float rm[4];
        rm[0] = fminf(left, a[0]);
        #pragma unroll
        for (int j = 1; j < 4; ++j) rm[j] = fminf(a[j - 1], a[j]);
        #pragma unroll
        for (int j = 0; j < 4; ++j) {
            er_prev[j] = fminf(rm_prev[j], rm[j]);
            rm_prev[j] = rm[j];
            x_prev[j]  = a[j];
        }
        float rmH = fminf(a[3], xH);
        erH_prev = fminf(rmH_prev, rmH);
        rmH_prev = rmH;
    }

    const int e_max = (r1 < HH) ? r1 : (HH - 1);

    // bumped pointers at row r0+1
    const float4* p  = (const float4*)(base + (size_t)(r0 + 1) * WW + c);
    const float*  pL = base + (size_t)(r0 + 1) * WW + haloL;
    const float*  pH = base + (size_t)(r0 + 1) * WW + haloR;

    // ---- batched steady state: 4 rows per iteration, loads front-issued ----
    for (int e0 = r0 + 1; e0 <= e_max; e0 += 4) {
        const int nrows = e_max - e0 + 1;        // uniform across warp; >=1

        // issue up to 4 row loads + halos back-to-back (high MLP)
        float4 v[4];
        float xLk[4], xHk[4];
        #pragma unroll
        for (int k = 0; k < 4; ++k) {
            if (k < nrows) {
                v[k]  = p[k * (WW / 4)];
                xLk[k] = doL ? pL[k * WW] : 0.f;
                xHk[k] = doH ? pH[k * WW] : 0.f;
            }
        }
        p += WW; pL += 4 * WW; pH += 4 * WW;     // bump 4 rows

        // process the batch from registers
        #pragma unroll
        for (int k = 0; k < 4; ++k) {
            if (k < nrows) {
                float a[4] = {v[k].x, v[k].y, v[k].z, v[k].w};

                // horizontal min (erosion offsets {-1,0}, reflect at col 0)
                float left = __shfl_up_sync(0xffffffffu, a[3], 1);
                if (lane == 0) left = leftEdge ? a[0] : xLk[k];
                float rm[4];
                rm[0] = fminf(left, a[0]);
                #pragma unroll
                for (int j = 1; j < 4; ++j) rm[j] = fminf(a[j - 1], a[j]);

                // vertical min -> eroded; vertical max with previous eroded
                float er[4], vm[4];
                #pragma unroll
                for (int j = 0; j < 4; ++j) {
                    er[j] = fminf(rm_prev[j], rm[j]);
                    vm[j] = fmaxf(er_prev[j], er[j]);
                }
                const float rmH = fminf(a[3], xHk[k]);
                const float erH = fminf(rmH_prev, rmH);
                const float vmH = fmaxf(erH_prev, erH);

                // horizontal max (dilation offsets {0,+1})
                float right = __shfl_down_sync(0xffffffffu, vm[0], 1);
                if (lane == 31) right = rightEdge ? vm[3] : vmH;
                float op[4];
                #pragma unroll
                for (int j = 0; j < 3; ++j) op[j] = fmaxf(vm[j], vm[j + 1]);
                op[3] = fmaxf(vm[3], right);

                #pragma unroll
                for (int j = 0; j < 4; ++j) {
                    const float d = x_prev[j] - op[j];
                    acc += d * d;
                }

                #pragma unroll
                for (int j = 0; j < 4; ++j) {
                    er_prev[j] = er[j];
                    rm_prev[j] = rm[j];
                    x_prev[j]  = a[j];
                }
                erH_prev = erH; rmH_prev = rmH;
            }
        }
    }

    // ---- epilogue: bottom band emits row H-1 (dilation clamps i+1 -> H-1) ----
    if (r1 == HH) {
        float right = __shfl_down_sync(0xffffffffu, er_prev[0], 1);
        if (lane == 31) right = rightEdge ? er_prev[3] : erH_prev;
        float op[4];
        #pragma unroll
        for (int j = 0; j < 3; ++j) op[j] = fmaxf(er_prev[j], er_prev[j + 1]);
        op[3] = fmaxf(er_prev[3], right);
        #pragma unroll
        for (int j = 0; j < 4; ++j) {
            const float d = x_prev[j] - op[j];
            acc += d * d;
        }
    }

    // ---- block reduction -> g_partials[blockIdx.x] ----
    #pragma unroll
    for (int o = 16; o > 0; o >>= 1)
        acc += __shfl_xor_sync(0xffffffffu, acc, o);

    __shared__ float s[WPB];
    __shared__ bool s_last;
    if (lane == 0) s[wid] = acc;
    __syncthreads();
    if (tid == 0) {
        float t = 0.f;
        #pragma unroll
        for (int i = 0; i < WPB; ++i) t += s[i];
        g_partials[blockIdx.x] = t;
        __threadfence();
        unsigned int old = atomicAdd(&g_counter, 1u);
        s_last = (old == NBLOCKS - 1);
    }
    __syncthreads();

    // ---- last block: deterministic fixed-order final reduction ----
    if (s_last) {
        float a = 0.f;
        for (int i = tid; i < NBLOCKS; i += 128) a += g_partials[i];
        #pragma unroll
        for (int o = 16; o > 0; o >>= 1)
            a += __shfl_xor_sync(0xffffffffu, a, o);
        __shared__ float s2[WPB];
        if (lane == 0) s2[wid] = a;
        __syncthreads();
        if (tid == 0) {
            float t = 0.f;
            #pragma unroll
            for (int i = 0; i < WPB; ++i) t += s2[i];
            out[0] = t * INV_N;
            g_counter = 0;   // self-reset for next launch / graph replay
        }
    }
}

extern "C" void kernel_launch(void* const* d_in, const int* in_sizes, int n_in,
                              void* d_out, int out_size) {
    (void)in_sizes; (void)n_in; (void)out_size;
    const float* labels = (const float*)d_in[0];
    float* out = (float*)d_out;
    open_mse_kernel<<<NBLOCKS, 128>>>(labels, out);
}

// round 11
// speedup vs baseline: 1.2823x; 1.0492x over previous
#include <cuda_runtime.h>

// labels [16, 8, 512, 512] float32
#define HH 512
#define WW 512
#define NIMG 128                  // 16*8
#define ROWS 32                   // output rows per band
#define BANDS (HH / ROWS)         // 16
#define STRIPS 2                  // 2 strips of 256 cols (8 cols/thread)
#define WPB 2                     // warps per block (64 threads)
#define NBLOCKS ((NIMG * BANDS * STRIPS) / WPB)   // 2048
#define INV_N (1.0f / 33554432.0f)

__device__ __align__(16) float g_partials[NBLOCKS];
__device__ unsigned int g_counter = 0;

__global__ __launch_bounds__(64) void open_mse_kernel(const float* __restrict__ x,
                                                      float* __restrict__ out) {
    const int tid  = threadIdx.x;
    const int wid  = tid >> 5;
    const int lane = tid & 31;
    const int gw   = blockIdx.x * WPB + wid;     // [0, 4096)

    const int strip = gw & 1;                    // 0..1
    const int band  = (gw >> 1) & (BANDS - 1);   // 0..15
    const int img   = gw >> 5;                   // 0..127

    const int c0 = strip * 256;
    const int r0 = band * ROWS;
    const int r1 = r0 + ROWS;
    const bool leftEdge  = (c0 == 0);
    const bool rightEdge = (c0 + 256 >= WW);

    const float* base = x + (size_t)img * (HH * WW);
    const int c = c0 + lane * 8;
    const bool doL = (lane == 0)  && !leftEdge;
    const bool doH = (lane == 31) && !rightEdge;
    const int haloL = leftEdge ? 0 : (c0 - 1);
    const int haloR = rightEdge ? (WW - 1) : (c0 + 256);

    float rm_prev[8], er_prev[8], x_prev[8];
    float rmH_prev, erH_prev = 0.f;
    float acc = 0.f;

    // ---- prologue: rowmin of row ra = max(r0-1, 0)  (reflect at top) ----
    {
        const int ra = (r0 > 0) ? (r0 - 1) : 0;
        const float4* pa = (const float4*)(base + (size_t)ra * WW + c);
        float4 u0 = pa[0], u1 = pa[1];
        float a[8] = {u0.x, u0.y, u0.z, u0.w, u1.x, u1.y, u1.z, u1.w};
        float xL = doL ? base[(size_t)ra * WW + haloL] : 0.f;
        float xH = doH ? base[(size_t)ra * WW + haloR] : 0.f;
        float left = __shfl_up_sync(0xffffffffu, a[7], 1);
        if (lane == 0) left = leftEdge ? a[0] : xL;
        rm_prev[0] = fminf(left, a[0]);
        #pragma unroll
        for (int j = 1; j < 8; ++j) rm_prev[j] = fminf(a[j - 1], a[j]);
        rmH_prev = fminf(a[7], xH);
    }

    // ---- peeled row r0: erosion only (no output) ----
    {
        const float4* pa = (const float4*)(base + (size_t)r0 * WW + c);
        float4 u0 = pa[0], u1 = pa[1];
        float a[8] = {u0.x, u0.y, u0.z, u0.w, u1.x, u1.y, u1.z, u1.w};
        float xL = doL ? base[(size_t)r0 * WW + haloL] : 0.f;
        float xH = doH ? base[(size_t)r0 * WW + haloR] : 0.f;
        float left = __shfl_up_sync(0xffffffffu, a[7], 1);
        if (lane == 0) left = leftEdge ? a[0] : xL;
        float rm[8];
        rm[0] = fminf(left, a[0]);
        #pragma unroll
        for (int j = 1; j < 8; ++j) rm[j] = fminf(a[j - 1], a[j]);
        #pragma unroll
        for (int j = 0; j < 8; ++j) {
            er_prev[j] = fminf(rm_prev[j], rm[j]);
            rm_prev[j] = rm[j];
            x_prev[j]  = a[j];
        }
        float rmH = fminf(a[7], xH);
        erH_prev = fminf(rmH_prev, rmH);
        rmH_prev = rmH;
    }

    const int e_max = (r1 < HH) ? r1 : (HH - 1);

    // bumped pointers at row r0+1
    const float4* p  = (const float4*)(base + (size_t)(r0 + 1) * WW + c);
    const float*  pL = base + (size_t)(r0 + 1) * WW + haloL;
    const float*  pH = base + (size_t)(r0 + 1) * WW + haloR;

    // ---- batched steady state: 4 rows/iter, 8 LDG.128 front-issued ----
    for (int e0 = r0 + 1; e0 <= e_max; e0 += 4) {
        const int nrows = e_max - e0 + 1;        // uniform across warp; >=1

        float4 v0[4], v1[4];
        float xLk[4], xHk[4];
        #pragma unroll
        for (int k = 0; k < 4; ++k) {
            if (k < nrows) {
                v0[k] = p[k * (WW / 4)];
                v1[k] = p[k * (WW / 4) + 1];
            }
        }
        #pragma unroll
        for (int k = 0; k < 4; ++k) {
            if (k < nrows) {
                xLk[k] = doL ? pL[k * WW] : 0.f;
                xHk[k] = doH ? pH[k * WW] : 0.f;
            }
        }
        p += WW; pL += 4 * WW; pH += 4 * WW;     // bump 4 rows

        #pragma unroll
        for (int k = 0; k < 4; ++k) {
            if (k < nrows) {
                float a[8] = {v0[k].x, v0[k].y, v0[k].z, v0[k].w,
                              v1[k].x, v1[k].y, v1[k].z, v1[k].w};

                // horizontal min (erosion offsets {-1,0}, reflect at col 0)
                float left = __shfl_up_sync(0xffffffffu, a[7], 1);
                if (lane == 0) left = leftEdge ? a[0] : xLk[k];
                float rm[8];
                rm[0] = fminf(left, a[0]);
                #pragma unroll
                for (int j = 1; j < 8; ++j) rm[j] = fminf(a[j - 1], a[j]);

                // vertical min -> eroded; vertical max with previous eroded
                float er[8], vm[8];
                #pragma unroll
                for (int j = 0; j < 8; ++j) {
                    er[j] = fminf(rm_prev[j], rm[j]);
                    vm[j] = fmaxf(er_prev[j], er[j]);
                }
                const float rmH = fminf(a[7], xHk[k]);
                const float erH = fminf(rmH_prev, rmH);
                const float vmH = fmaxf(erH_prev, erH);

                // horizontal max (dilation offsets {0,+1})
                float right = __shfl_down_sync(0xffffffffu, vm[0], 1);
                if (lane == 31) right = rightEdge ? vm[7] : vmH;
                float op[8];
                #pragma unroll
                for (int j = 0; j < 7; ++j) op[j] = fmaxf(vm[j], vm[j + 1]);
                op[7] = fmaxf(vm[7], right);

                #pragma unroll
                for (int j = 0; j < 8; ++j) {
                    const float d = x_prev[j] - op[j];
                    acc += d * d;
                }

                #pragma unroll
                for (int j = 0; j < 8; ++j) {
                    er_prev[j] = er[j];
                    rm_prev[j] = rm[j];
                    x_prev[j]  = a[j];
                }
                erH_prev = erH; rmH_prev = rmH;
            }
        }
    }

    // ---- epilogue: bottom band emits row H-1 (dilation clamps i+1 -> H-1) ----
    if (r1 == HH) {
        float right = __shfl_down_sync(0xffffffffu, er_prev[0], 1);
        if (lane == 31) right = rightEdge ? er_prev[7] : erH_prev;
        float op[8];
        #pragma unroll
        for (int j = 0; j < 7; ++j) op[j] = fmaxf(er_prev[j], er_prev[j + 1]);
        op[7] = fmaxf(er_prev[7], right);
        #pragma unroll
        for (int j = 0; j < 8; ++j) {
            const float d = x_prev[j] - op[j];
            acc += d * d;
        }
    }

    // ---- block reduction -> g_partials[blockIdx.x] ----
    #pragma unroll
    for (int o = 16; o > 0; o >>= 1)
        acc += __shfl_xor_sync(0xffffffffu, acc, o);

    __shared__ float s[WPB];
    __shared__ bool s_last;
    if (lane == 0) s[wid] = acc;
    __syncthreads();
    if (tid == 0) {
        float t = s[0] + s[1];
        g_partials[blockIdx.x] = t;
        __threadfence();
        unsigned int old = atomicAdd(&g_counter, 1u);
        s_last = (old == NBLOCKS - 1);
    }
    __syncthreads();

    // ---- last block: deterministic fixed-order final reduction ----
    if (s_last) {
        const float4* gp4 = (const float4*)g_partials;
        float a = 0.f;
        for (int i = tid; i < NBLOCKS / 4; i += 64) {   // 8 float4 per thread
            float4 v = gp4[i];
            a += (v.x + v.y) + (v.z + v.w);
        }
        #pragma unroll
        for (int o = 16; o > 0; o >>= 1)
            a += __shfl_xor_sync(0xffffffffu, a, o);
        __shared__ float s2[WPB];
        if (lane == 0) s2[wid] = a;
        __syncthreads();
        if (tid == 0) {
            out[0] = (s2[0] + s2[1]) * INV_N;
            g_counter = 0;   // self-reset for next launch / graph replay
        }
    }
}

extern "C" void kernel_launch(void* const* d_in, const int* in_sizes, int n_in,
                              void* d_out, int out_size) {
    (void)in_sizes; (void)n_in; (void)out_size;
    const float* labels = (const float*)d_in[0];
    float* out = (float*)d_out;
    open_mse_kernel<<<NBLOCKS, 64>>>(labels, out);
}

// round 13
// speedup vs baseline: 1.4530x; 1.1331x over previous
#include <cuda_runtime.h>

// labels [16, 8, 512, 512] float32
#define HH 512
#define WW 512
#define NIMG 128
#define ROWS 32                       // output rows per band
#define BANDS (HH / ROWS)             // 16
#define NBLOCKS (NIMG * BANDS)        // 2048 CTAs
#define NTHR 128                      // 4 warps; 4 cols/thread over full 512 width
#define NSTG 6                        // SMEM ring stages
#define SROWS 4                       // rows per stage
#define TSTAGES 9                     // ceil(36/4); rows t=0..35 issued, t<=33 used
#define INV_N (1.0f / 33554432.0f)

__device__ __align__(16) float g_partials[NBLOCKS];
__device__ unsigned int g_counter = 0;

__device__ __forceinline__ void cp16(unsigned sa, const float* g) {
    asm volatile("cp.async.cg.shared.global [%0], [%1], 16;" :: "r"(sa), "l"(g));
}
__device__ __forceinline__ void cpcommit() {
    asm volatile("cp.async.commit_group;" ::: "memory");
}
__device__ __forceinline__ void cpwait() {                 // <= NSTG-2 groups pending
    asm volatile("cp.async.wait_group 4;" ::: "memory");
}

__global__ __launch_bounds__(NTHR) void open_mse_kernel(const float* __restrict__ x,
                                                        float* __restrict__ out) {
    __shared__ float smem[NSTG * SROWS][WW];               // exactly 48 KB
    const int tid  = threadIdx.x;
    const int wid  = tid >> 5;
    const int lane = tid & 31;
    const int band = blockIdx.x & (BANDS - 1);
    const int img  = blockIdx.x >> 4;                      // BANDS = 16
    const int r0   = band * ROWS;
    const bool bottom = (r0 + ROWS == HH);
    const int t_stop  = bottom ? ROWS : (ROWS + 1);        // last erosion-row index t

    const float* base = x + (size_t)img * (HH * WW);
    const int c  = tid * 4;
    const int cL = (c == 0) ? 0 : (c - 1);                 // erosion reflect at col 0
    const int cR = (c + 4 < WW) ? (c + 4) : (WW - 2);      // makes rm[4]=rm[3] at right edge

    // ---- async producer: stage s = rows t in [4s, 4s+3], global row clamp(r0-1+t) ----
    auto issue = [&](int s) {
        #pragma unroll
        for (int k = 0; k < SROWS; ++k) {
            int t = s * SROWS + k;
            int g = r0 - 1 + t;
            g = g < 0 ? 0 : (g > HH - 1 ? HH - 1 : g);
            unsigned sa = (unsigned)__cvta_generic_to_shared(&smem[(s % NSTG) * SROWS + k][c]);
            cp16(sa, base + (size_t)g * WW + c);
        }
        cpcommit();
    };

    #pragma unroll
    for (int s = 0; s < NSTG - 1; ++s) issue(s);           // prefetch stages 0..4

    float rm_prev[5], er_prev[5], x_prev[4];
    float acc = 0.f;

    // fully local per-row update: 4 output cols from a 6-float SMEM window
    auto full_row = [&](const float* row) {
        float4 av = *(const float4*)(row + c);
        float a0 = av.x, a1 = av.y, a2 = av.z, a3 = av.w;
        float xm1 = row[cL], x4r = row[cR];
        float rm[5];
        rm[0] = fminf(xm1, a0); rm[1] = fminf(a0, a1); rm[2] = fminf(a1, a2);
        rm[3] = fminf(a2, a3);  rm[4] = fminf(a3, x4r);
        float er[5], vm[5];
        #pragma unroll
        for (int j = 0; j < 5; ++j) {
            er[j] = fminf(rm_prev[j], rm[j]);
            vm[j] = fmaxf(er_prev[j], er[j]);
        }
        #pragma unroll
        for (int j = 0; j < 4; ++j) {
            float op = fmaxf(vm[j], vm[j + 1]);
            float d  = x_prev[j] - op;
            acc += d * d;
        }
        #pragma unroll
        for (int j = 0; j < 5; ++j) { rm_prev[j] = rm[j]; er_prev[j] = er[j]; }
        x_prev[0] = a0; x_prev[1] = a1; x_prev[2] = a2; x_prev[3] = a3;
    };

    // ---- stage 0: prologue row, first erosion row, two full rows ----
    cpwait();
    __syncthreads();
    issue(NSTG - 1);                                       // stage 5
    {
        // t=0: rowmin of row max(r0-1,0) (reflect at top)
        const float* row = smem[0];
        {
            float4 av = *(const float4*)(row + c);
            float a0 = av.x, a1 = av.y, a2 = av.z, a3 = av.w;
            float xm1 = row[cL], x4r = row[cR];
            rm_prev[0] = fminf(xm1, a0); rm_prev[1] = fminf(a0, a1);
            rm_prev[2] = fminf(a1, a2);  rm_prev[3] = fminf(a2, a3);
            rm_prev[4] = fminf(a3, x4r);
        }
        // t=1: erosion row r0 (no output)
        row = smem[1];
        {
            float4 av = *(const float4*)(row + c);
            float a0 = av.x, a1 = av.y, a2 = av.z, a3 = av.w;
            float xm1 = row[cL], x4r = row[cR];
            float rm[5];
            rm[0] = fminf(xm1, a0); rm[1] = fminf(a0, a1); rm[2] = fminf(a1, a2);
            rm[3] = fminf(a2, a3);  rm[4] = fminf(a3, x4r);
            #pragma unroll
            for (int j = 0; j < 5; ++j) { er_prev[j] = fminf(rm_prev[j], rm[j]); rm_prev[j] = rm[j]; }
            x_prev[0] = a0; x_prev[1] = a1; x_prev[2] = a2; x_prev[3] = a3;
        }
        full_row(smem[2]);                                 // t=2
        full_row(smem[3]);                                 // t=3
    }

    // ---- steady stages 1..8 ----
    for (int s = 1; s < TSTAGES; ++s) {
        cpwait();
        __syncthreads();
        if (s + NSTG - 1 < TSTAGES) issue(s + NSTG - 1); else cpcommit();
        const int sb = (s % NSTG) * SROWS;
        #pragma unroll
        for (int k = 0; k < SROWS; ++k) {
            const int t = s * SROWS + k;
            if (t <= t_stop) full_row(smem[sb + k]);
        }
    }

    // ---- bottom band: emit row H-1 (dilation clamps row 512 -> 511) ----
    if (bottom) {
        #pragma unroll
        for (int j = 0; j < 4; ++j) {
            float op = fmaxf(er_prev[j], er_prev[j + 1]);
            float d  = x_prev[j] - op;
            acc += d * d;
        }
    }

    // ---- block reduction (reuse smem ring as scratch) ----
    #pragma unroll
    for (int o = 16; o > 0; o >>= 1)
        acc += __shfl_xor_sync(0xffffffffu, acc, o);

    __syncthreads();                                       // everyone done reading ring
    float* sm = &smem[0][0];
    if (lane == 0) sm[wid] = acc;
    __syncthreads();
    if (tid == 0) {
        float t = (sm[0] + sm[1]) + (sm[2] + sm[3]);
        g_partials[blockIdx.x] = t;
        __threadfence();
        unsigned int old = atomicAdd(&g_counter, 1u);
        sm[4] = (old == NBLOCKS - 1) ? 1.f : 0.f;
    }
    __syncthreads();

    // ---- last block: deterministic fixed-order final reduction ----
    if (sm[4] != 0.f) {
        const float4* gp4 = (const float4*)g_partials;
        float a = 0.f;
        #pragma unroll
        for (int i = 0; i < NBLOCKS / 4 / NTHR; ++i) {     // 4 iters
            float4 v = gp4[tid + i * NTHR];
            a += (v.x + v.y) + (v.z + v.w);
        }
        #pragma unroll
        for (int o = 16; o > 0; o >>= 1)
            a += __shfl_xor_sync(0xffffffffu, a, o);
        __syncthreads();
        if (lane == 0) sm[8 + wid] = a;
        __syncthreads();
        if (tid == 0) {
            out[0] = ((sm[8] + sm[9]) + (sm[10] + sm[11])) * INV_N;
            g_counter = 0;                                 // self-reset for graph replay
        }
    }
}

extern "C" void kernel_launch(void* const* d_in, const int* in_sizes, int n_in,
                              void* d_out, int out_size) {
    (void)in_sizes; (void)n_in; (void)out_size;
    const float* labels = (const float*)d_in[0];
    float* out = (float*)d_out;
    open_mse_kernel<<<NBLOCKS, NTHR>>>(labels, out);
}